// round 14
// baseline (speedup 1.0000x reference)
#include <cuda_runtime.h>
#include <math.h>

// ---------------------------------------------------------------------------
// HardConstrainedMLP. proj_pinv(s) = s @ P + Q,  P idempotent, Q P = 0 =>
//   z_{k+1} = 0.7 z_k + C0 + 1.8 * (delta_k[250:] @ P[250:,:])
// Solver: 128 CTAs x 8 rows x 512 thr. P2 = P[250:,:] k-pair interleaved.
// NEW: cross-iteration continuous cp.async ring (never drains; prefetches for
// iter k+1 overlap iter k's epilogue) + 28-of-128 kp persistent smem cache.
// Precompute compressed to 3 launches (C0 via W3P trick) so ncu -s 5 -c 1
// lands on a solver chunk.
// ---------------------------------------------------------------------------

#define BATCH       1024
#define MDIM        250
#define DTOT        500
#define HDIM        512
#define NITER       1000
#define NCHUNK      4
#define CHUNK       (NITER / NCHUNK)
#define ROWS_PER_CTA 8
#define SOLVER_CTAS (BATCH / ROWS_PER_CTA)
#define NTHR        512
#define NSTR        25          // streamed 2-kp steps per kgroup (50 kp)
#define NCACHE      7           // cached 2-kp steps per kgroup  (14 kp)

#define OMEGA_F 1.8f
#define ALPHA_F (1.0f / 1.2f)

typedef unsigned long long ull;

#define FFMA2(d, a, b) \
    asm("fma.rn.f32x2 %0, %1, %2, %0;" : "+l"(d) : "l"(a), "l"(b))

__device__ __forceinline__ float2 f32x2_unpack(ull v) {
    float2 r;
    asm("mov.b64 {%0, %1}, %2;" : "=f"(r.x), "=f"(r.y) : "l"(v));
    return r;
}

__device__ __forceinline__ void cp_async16(unsigned sa, const void* g) {
    asm volatile("cp.async.cg.shared.global [%0], [%1], 16;" :: "r"(sa), "l"(g));
}
#define CP_COMMIT() asm volatile("cp.async.commit_group;")
#define CP_WAIT3()  asm volatile("cp.async.wait_group 3;")
#define CP_WAIT0()  asm volatile("cp.async.wait_group 0;")

// Scratch (device globals; zero-initialized, no runtime allocation)
__device__ float g_X1 [BATCH * HDIM];
__device__ float g_X2 [BATCH * HDIM];
__device__ float g_Ys [BATCH * DTOT];
__device__ float g_Q  [BATCH * DTOT];
__device__ float g_C0 [BATCH * DTOT];      // 0.3 Q - 1.8 Ys@P
__device__ float g_S  [BATCH * DTOT];
__device__ float g_Z  [BATCH * DTOT];
__device__ float g_Pn [DTOT * DTOT];       // P, plain row-major
__device__ float g_W3P[HDIM * DTOT];       // (W3 @ P) / 6
__device__ float g_b3P[DTOT];              // (b3 @ P) / 6
__device__ float g_P2 [128 * 1024];        // P[250:,:], k-pair interleaved:
                                           // [kp*1024 + 2c + par]

// ---------------------------------------------------------------------------
// Precompute GEMM.
//  mode: 1 relu, 2 *(1/6), 4 P dual-store (E plain + C interleaved rows>=250),
//        6 C0 = 0.3*E - 1.8*(acc+bias)
// ---------------------------------------------------------------------------
__device__ void gemm_dev(const float* __restrict__ A, const float* __restrict__ A2,
                         const float* __restrict__ B, const float* __restrict__ bias,
                         float* __restrict__ C, float* __restrict__ E,
                         int M, int N, int K, int mode, int bT, int aT)
{
    __shared__ float As[16][64];
    __shared__ float Bs[16][68];
    const int tid = threadIdx.x;
    const int tx = tid & 15, ty = tid >> 4;
    const int m0 = blockIdx.y * 64, n0 = blockIdx.x * 64;

    float acc[4][4];
    #pragma unroll
    for (int i = 0; i < 4; i++)
        #pragma unroll
        for (int j = 0; j < 4; j++) acc[i][j] = 0.f;

    for (int k0 = 0; k0 < K; k0 += 16) {
        #pragma unroll
        for (int i = 0; i < 4; i++) {
            int idx = tid + i * 256;
            int mr = idx >> 4, kk = idx & 15;
            int mg = m0 + mr, kg = k0 + kk;
            float av = 0.f;
            if (mg < M && kg < K) {
                if (aT)       av = A[(size_t)kg * M + mg];
                else if (A2)  av = (kg < MDIM) ? A[(size_t)mg * MDIM + kg]
                                               : A2[(size_t)mg * MDIM + (kg - MDIM)];
                else          av = A[(size_t)mg * K + kg];
            }
            As[kk][mr] = av;
        }
        #pragma unroll
        for (int i = 0; i < 4; i++) {
            int idx = tid + i * 256;
            if (!bT) {
                int kk = idx >> 6, cg = idx & 63;
                int kgl = k0 + kk, cgl = n0 + cg;
                Bs[kk][cg] = (kgl < K && cgl < N) ? B[(size_t)kgl * N + cgl] : 0.f;
            } else {
                int cg = idx >> 4, kk = idx & 15;
                int kgl = k0 + kk, cgl = n0 + cg;
                Bs[kk][cg] = (kgl < K && cgl < N) ? B[(size_t)cgl * K + kgl] : 0.f;
            }
        }
        __syncthreads();
        #pragma unroll
        for (int kk = 0; kk < 16; kk++) {
            float a[4], bb[4];
            #pragma unroll
            for (int i = 0; i < 4; i++) a[i] = As[kk][ty * 4 + i];
            #pragma unroll
            for (int j = 0; j < 4; j++) bb[j] = Bs[kk][tx * 4 + j];
            #pragma unroll
            for (int i = 0; i < 4; i++)
                #pragma unroll
                for (int j = 0; j < 4; j++) acc[i][j] += a[i] * bb[j];
        }
        __syncthreads();
    }

    #pragma unroll
    for (int i = 0; i < 4; i++) {
        int mg = m0 + ty * 4 + i;
        if (mg >= M) continue;
        #pragma unroll
        for (int j = 0; j < 4; j++) {
            int ng = n0 + tx * 4 + j;
            if (ng >= N) continue;
            float v = acc[i][j];
            if (bias) v += bias[ng];
            if (mode == 1)      v = fmaxf(v, 0.f);
            else if (mode == 2) v *= (1.0f / 6.0f);
            if (mode == 4) {
                v = ((mg == ng) ? 1.f : 0.f) - v;
                E[(size_t)mg * DTOT + ng] = v;
                if (mg >= MDIM)
                    C[(size_t)((mg - MDIM) >> 1) * 1024 + ng * 2 + ((mg - MDIM) & 1)] = v;
            } else if (mode == 6) {
                C[(size_t)mg * N + ng] = 0.3f * E[(size_t)mg * N + ng] - 1.8f * v;
            } else {
                C[(size_t)mg * N + ng] = v;
            }
        }
    }
}

// L1: X1 | Q | P (dual store)
__global__ void precompute1(const float* b, const float* cin,
                            const float* W1, const float* b1,
                            const float* Aaug, const float* Ainv,
                            float* X1, float* Q, float* P2, float* Pn)
{
    int z = blockIdx.z;
    if (z == 0) {
        gemm_dev(b, cin, W1, b1, X1, nullptr, BATCH, HDIM, DTOT, 1, 0, 0);
    } else if (z == 1) {
        gemm_dev(b, nullptr, Ainv, nullptr, Q, nullptr, BATCH, DTOT, MDIM, 0, 1, 0);
    } else {
        if (blockIdx.y >= 8) return;
        gemm_dev(Aaug, nullptr, Ainv, nullptr, P2, Pn, DTOT, DTOT, MDIM, 4, 1, 1);
    }
}

// L2: X2 | W3P' = (W3@P)/6 | b3P' = (b3@P)/6
__global__ void precompute2(const float* X1, const float* W2, const float* b2,
                            const float* W3, const float* b3, const float* Pn,
                            float* X2, float* W3P, float* b3P)
{
    int z = blockIdx.z;
    if (z == 0) {
        gemm_dev(X1, nullptr, W2, b2, X2, nullptr, BATCH, HDIM, HDIM, 1, 0, 0);
    } else if (z == 1) {
        if (blockIdx.y >= 8) return;
        gemm_dev(W3, nullptr, Pn, nullptr, W3P, nullptr, HDIM, DTOT, DTOT, 2, 0, 0);
    } else {
        if (blockIdx.y >= 1) return;
        gemm_dev(b3, nullptr, Pn, nullptr, b3P, nullptr, 1, DTOT, DTOT, 2, 0, 0);
    }
}

// L3: Ys | C0 = 0.3 Q - 1.8 (X2 @ W3P' + b3P')
__global__ void precompute3(const float* X2, const float* W3, const float* b3,
                            const float* W3P, const float* b3P, const float* Q,
                            float* Ys, float* C0)
{
    int z = blockIdx.z;
    if (z == 0) {
        gemm_dev(X2, nullptr, W3, b3, Ys, nullptr, BATCH, DTOT, HDIM, 2, 0, 0);
    } else {
        gemm_dev(X2, nullptr, W3P, b3P, C0, const_cast<float*>(Q),
                 BATCH, DTOT, HDIM, 6, 0, 0);
    }
}

// ---------------------------------------------------------------------------
// Solver smem (floats):
//  Dsm[2048] | Pz[8192] | red[128] nrm[8] tls[8] pad->10496 |
//  Pcs[28*1024=28672] | ring[16 warps * 4 slots * 256] = 16384
//  total 55552 f = 222,208 B
// ---------------------------------------------------------------------------
#define SMEM_FLOATS 55552
#define SMEM_BYTES  (SMEM_FLOATS * 4)

__device__ __forceinline__ float soc_elem(float tp, int c, float nu, float tt)
{
    if (c < MDIM) return tp;
    if (nu <= tt) return tp;
    if (nu <= -tt) return 0.f;
    float h = 0.5f * (tt + nu);
    return (c == DTOT - 1) ? h : h * tp / (nu + 1e-12f);
}

// Issue 2 cp.async (2 kp, this warp's 64-col slice = 1KB/warp) for step st.
__device__ __forceinline__ void issue_step(unsigned ring_sa, int slot, int st,
                                           int g, int cg, int lane)
{
    const float* src = g_P2 + (g * 64 + 2 * st) * 1024 + cg * 128 + lane * 4;
    unsigned dst = ring_sa + (unsigned)(slot * 1024 + lane * 16);
    cp_async16(dst,       src);          // kp0
    cp_async16(dst + 512, src + 1024);   // kp1
}

// Partial w = delta @ P2 over kgroup g for 2 cols x 8 rows -> Pz.
// Continuous ring: on entry 3 steps are in flight; on exit, steps 0..2 of the
// NEXT gemm are in flight. Returns updated slot counter.
__device__ __forceinline__ int gemm_partial(const float* __restrict__ Dsm,
                                            const float* __restrict__ Pcs,
                                            float* __restrict__ ringw,
                                            float* __restrict__ Pz,
                                            int ctr, int g, int cg, int lane)
{
    unsigned ring_sa = (unsigned)__cvta_generic_to_shared(ringw);

    ull acc[8][2];
    #pragma unroll
    for (int r = 0; r < 8; r++) { acc[r][0] = 0ull; acc[r][1] = 0ull; }

    // ---- streamed phase: 25 steps x 2 kp (kp 0..49 of group) ----
    #pragma unroll 5
    for (int st = 0; st < NSTR; st++) {
        int pf = st + 3; if (pf >= NSTR) pf -= NSTR;       // wraps to next iter
        issue_step(ring_sa, (ctr + 3) & 3, pf, g, cg, lane);
        CP_COMMIT();
        CP_WAIT3();                                        // step st's data ready
        // own-lane reads only; no syncwarp needed

        const float* slotp = ringw + (ctr & 3) * 256 + lane * 4;
        ulonglong2 p0 = *reinterpret_cast<const ulonglong2*>(slotp);         // kp0
        ulonglong2 p1 = *reinterpret_cast<const ulonglong2*>(slotp + 128);   // kp1

        const int kf = g * 128 + 4 * st;
        #pragma unroll
        for (int r = 0; r < 8; r++) {
            ulonglong2 sv = *reinterpret_cast<const ulonglong2*>(&Dsm[r * 256 + kf]);
            FFMA2(acc[r][0], sv.x, p0.x);  FFMA2(acc[r][1], sv.x, p0.y);
            FFMA2(acc[r][0], sv.y, p1.x);  FFMA2(acc[r][1], sv.y, p1.y);
        }
        ctr++;
    }

    // ---- cached phase: 7 steps x 2 kp (kp 50..63 of group, smem-resident) ----
    #pragma unroll
    for (int j = 0; j < NCACHE; j++) {
        const float* cp0 = &Pcs[(g * 14 + 2 * j) * 1024 + cg * 128 + lane * 4];
        ulonglong2 p0 = *reinterpret_cast<const ulonglong2*>(cp0);
        ulonglong2 p1 = *reinterpret_cast<const ulonglong2*>(cp0 + 1024);
        const int kf = g * 128 + 100 + 4 * j;
        #pragma unroll
        for (int r = 0; r < 8; r++) {
            ulonglong2 sv = *reinterpret_cast<const ulonglong2*>(&Dsm[r * 256 + kf]);
            FFMA2(acc[r][0], sv.x, p0.x);  FFMA2(acc[r][1], sv.x, p0.y);
            FFMA2(acc[r][0], sv.y, p1.x);  FFMA2(acc[r][1], sv.y, p1.y);
        }
    }

    float* dst = &Pz[g * 4096 + cg * 64 + 2 * lane];
    #pragma unroll
    for (int r = 0; r < 8; r++) {
        float2 u0 = f32x2_unpack(acc[r][0]);
        float2 u1 = f32x2_unpack(acc[r][1]);
        float2 v; v.x = u0.x + u0.y; v.y = u1.x + u1.y;
        *reinterpret_cast<float2*>(&dst[r * 512]) = v;
    }
    return ctr;
}

__global__ void __launch_bounds__(NTHR, 1) solver_kernel(float* __restrict__ out,
                                                         int start_it, int end_it)
{
    extern __shared__ float sm[];
    float* Dsm  = sm;              // 2048 (8 rows x 256 local-k, zero-padded)
    float* Pz   = sm + 2048;       // 8192
    float* red  = sm + 10240;      // 128
    float* nrm  = sm + 10368;      // 8
    float* tls  = sm + 10376;      // 8
    float* Pcs  = sm + 10496;      // 28*1024
    float* ring = sm + 39168;      // 16*1024

    const int t = threadIdx.x;
    const int w = t >> 5, lane = t & 31;
    const int g = w & 1, cg = w >> 1;
    float* ringw = ring + w * 1024;
    const int row0 = blockIdx.x * ROWS_PER_CTA;
    const int c = t;
    const bool act = (c < DTOT);

    // persistent per-thread state
    float s[8], z[8], ys[8], c0[8];
    #pragma unroll
    for (int r = 0; r < 8; r++) {
        if (act) {
            int idx = (row0 + r) * DTOT + c;
            ys[r] = g_Ys[idx];
            c0[r] = g_C0[idx];
            if (start_it == 0) { s[r] = 0.f; z[r] = g_Q[idx]; }
            else               { s[r] = g_S[idx]; z[r] = g_Z[idx]; }
        } else { s[r] = 0.f; z[r] = 0.f; ys[r] = 0.f; c0[r] = 0.f; }
    }

    // Dsm zero; P cache fill (kp = group*64 + 50 + j, j<14)
    for (int i = t; i < ROWS_PER_CTA * 256; i += NTHR) Dsm[i] = 0.f;
    {
        float4* dstv = reinterpret_cast<float4*>(Pcs);
        #pragma unroll 1
        for (int i4 = t; i4 < 28 * 256; i4 += NTHR) {
            int sidx = i4 >> 8, within = i4 & 255;
            int kp = (sidx / 14) * 64 + 50 + (sidx % 14);
            dstv[i4] = *reinterpret_cast<const float4*>(&g_P2[kp * 1024 + within * 4]);
        }
    }
    __syncthreads();

    // ring prologue: steps 0..2 in flight (stays primed across iterations)
    int ctr = 0;
    {
        unsigned ring_sa = (unsigned)__cvta_generic_to_shared(ringw);
        #pragma unroll
        for (int d = 0; d < 3; d++) { issue_step(ring_sa, d, d, g, cg, lane); CP_COMMIT(); }
    }

    const bool in_u = act && (c >= MDIM) && (c != DTOT - 1);

    for (int it = start_it; it < end_it; ++it) {
        // ---- elementwise: toproj + ssq partials ----
        float tp[8], val[8];
        #pragma unroll
        for (int r = 0; r < 8; r++) {
            tp[r]  = act ? (ALPHA_F * (2.f * z[r] - s[r]) - ys[r]) : 0.f;
            val[r] = in_u ? tp[r] * tp[r] : 0.f;
        }
        #pragma unroll
        for (int off = 16; off; off >>= 1)
            #pragma unroll
            for (int r = 0; r < 8; r++)
                val[r] += __shfl_down_sync(0xffffffffu, val[r], off);
        if (lane == 0) {
            #pragma unroll
            for (int r = 0; r < 8; r++) red[w * 8 + r] = val[r];
        }
        if (t == DTOT - 1) {
            #pragma unroll
            for (int r = 0; r < 8; r++) tls[r] = tp[r];
        }
        __syncthreads();                               // B1
        if (w < 8 && lane < 16) {                      // warp w reduces row w
            float sv = red[lane * 8 + w];
            #pragma unroll
            for (int off = 8; off; off >>= 1)
                sv += __shfl_down_sync(0x0000ffffu, sv, off);
            if (lane == 0) nrm[w] = sqrtf(sv);
        }
        __syncthreads();                               // B2
        // ---- tk, delta, s-update ----
        if (act) {
            #pragma unroll
            for (int r = 0; r < 8; r++) {
                float tk = soc_elem(tp[r], c, nrm[r], tls[r]);
                s[r] += OMEGA_F * (tk - z[r]);
                if (c >= MDIM) Dsm[r * 256 + (c - MDIM)] = tk - tp[r];
            }
        }
        __syncthreads();                               // B3: delta visible
        ctr = gemm_partial(Dsm, Pcs, ringw, Pz, ctr, g, cg, lane);
        __syncthreads();                               // B4: partials ready
        // ---- z-recursion ----
        if (act) {
            #pragma unroll
            for (int r = 0; r < 8; r++) {
                float wv = Pz[r * 512 + c] + Pz[4096 + r * 512 + c];
                z[r] = 0.7f * z[r] + c0[r] + 1.8f * wv;
            }
        }
    }

    CP_WAIT0();   // drain the primed ring before exit

    if (end_it == NITER) {
        if (act) {
            #pragma unroll
            for (int r = 0; r < 8; r++)
                out[(row0 + r) * DTOT + c] = z[r];
        }
    } else if (act) {
        #pragma unroll
        for (int r = 0; r < 8; r++) {
            int idx = (row0 + r) * DTOT + c;
            g_S[idx] = s[r];
            g_Z[idx] = z[r];
        }
    }
}

// ---------------------------------------------------------------------------
extern "C" void kernel_launch(void* const* d_in, const int* in_sizes, int n_in,
                              void* d_out, int out_size)
{
    const float* b    = (const float*)d_in[0];
    const float* cin  = (const float*)d_in[1];
    const float* W1   = (const float*)d_in[2];
    const float* b1   = (const float*)d_in[3];
    const float* W2   = (const float*)d_in[4];
    const float* b2   = (const float*)d_in[5];
    const float* W3   = (const float*)d_in[6];
    const float* b3   = (const float*)d_in[7];
    const float* Aaug = (const float*)d_in[8];
    const float* Ainv = (const float*)d_in[9];
    float* out = (float*)d_out;

    float *X1, *X2, *Ys, *Q, *C0, *Pn, *P2, *W3P, *b3P;
    cudaGetSymbolAddress((void**)&X1,  g_X1);
    cudaGetSymbolAddress((void**)&X2,  g_X2);
    cudaGetSymbolAddress((void**)&Ys,  g_Ys);
    cudaGetSymbolAddress((void**)&Q,   g_Q);
    cudaGetSymbolAddress((void**)&C0,  g_C0);
    cudaGetSymbolAddress((void**)&Pn,  g_Pn);
    cudaGetSymbolAddress((void**)&P2,  g_P2);
    cudaGetSymbolAddress((void**)&W3P, g_W3P);
    cudaGetSymbolAddress((void**)&b3P, g_b3P);

    cudaFuncSetAttribute(solver_kernel,
                         cudaFuncAttributeMaxDynamicSharedMemorySize, SMEM_BYTES);

    // L1: X1 | Q | P
    precompute1<<<dim3(8, 16, 3), 256>>>(b, cin, W1, b1, Aaug, Ainv, X1, Q, P2, Pn);
    // L2: X2 | W3P' | b3P'
    precompute2<<<dim3(8, 16, 3), 256>>>(X1, W2, b2, W3, b3, Pn, X2, W3P, b3P);
    // L3: Ys | C0
    precompute3<<<dim3(8, 16, 2), 256>>>(X2, W3, b3, W3P, b3P, Q, Ys, C0);
    // L4..L7: solver chunks (global launch #6 = chunk under ncu -s 5 -c 1)
    for (int ch = 0; ch < NCHUNK; ch++)
        solver_kernel<<<SOLVER_CTAS, NTHR, SMEM_BYTES>>>(out, ch * CHUNK, (ch + 1) * CHUNK);
}

// round 15
// speedup vs baseline: 1.0618x; 1.0618x over previous
#include <cuda_runtime.h>
#include <math.h>

// ---------------------------------------------------------------------------
// HardConstrainedMLP. proj_pinv(s) = s @ P + Q,  P idempotent, Q P = 0 =>
//   z_{k+1} = 0.7 z_k + C0 + 1.8 * (delta_k[250:] @ P[250:,:])
// Solver: 128 CTAs x 8 rows x 512 thr (16 warps: g = w&1 kgroup, cg = w>>1).
// R15: streamed P goes LDG.128 -> register double-buffer (NO smem bounce;
// halves crossbar phases vs the cp.async ring), prefetch wraps across
// iterations; freed smem -> 40-kp read-only P cache.
// ---------------------------------------------------------------------------

#define BATCH       1024
#define MDIM        250
#define DTOT        500
#define HDIM        512
#define NITER       1000
#define NCHUNK      4
#define CHUNK       (NITER / NCHUNK)
#define ROWS_PER_CTA 8
#define SOLVER_CTAS (BATCH / ROWS_PER_CTA)
#define NTHR        512
#define NSTR        22          // streamed 2-kp steps per kgroup (44 kp)
#define NCACHE      10          // cached 2-kp steps per kgroup  (20 kp)

#define OMEGA_F 1.8f
#define ALPHA_F (1.0f / 1.2f)

typedef unsigned long long ull;

#define FFMA2(d, a, b) \
    asm("fma.rn.f32x2 %0, %1, %2, %0;" : "+l"(d) : "l"(a), "l"(b))

__device__ __forceinline__ float2 f32x2_unpack(ull v) {
    float2 r;
    asm("mov.b64 {%0, %1}, %2;" : "=f"(r.x), "=f"(r.y) : "l"(v));
    return r;
}

// Scratch (device globals; zero-initialized, no runtime allocation)
__device__ float g_X1 [BATCH * HDIM];
__device__ float g_X2 [BATCH * HDIM];
__device__ float g_Ys [BATCH * DTOT];
__device__ float g_Q  [BATCH * DTOT];
__device__ float g_C0 [BATCH * DTOT];      // 0.3 Q - 1.8 Ys@P
__device__ float g_S  [BATCH * DTOT];
__device__ float g_Z  [BATCH * DTOT];
__device__ float g_Pn [DTOT * DTOT];       // P, plain row-major
__device__ float g_W3P[HDIM * DTOT];       // (W3 @ P) / 6
__device__ float g_b3P[DTOT];              // (b3 @ P) / 6
__device__ float g_P2 [128 * 1024];        // P[250:,:], k-pair interleaved:
                                           // [kp*1024 + 2c + par]

// ---------------------------------------------------------------------------
// Precompute GEMM.
//  mode: 1 relu, 2 *(1/6), 4 P dual-store (E plain + C interleaved rows>=250),
//        6 C0 = 0.3*E - 1.8*(acc+bias)
// ---------------------------------------------------------------------------
__device__ void gemm_dev(const float* __restrict__ A, const float* __restrict__ A2,
                         const float* __restrict__ B, const float* __restrict__ bias,
                         float* __restrict__ C, float* __restrict__ E,
                         int M, int N, int K, int mode, int bT, int aT)
{
    __shared__ float As[16][64];
    __shared__ float Bs[16][68];
    const int tid = threadIdx.x;
    const int tx = tid & 15, ty = tid >> 4;
    const int m0 = blockIdx.y * 64, n0 = blockIdx.x * 64;

    float acc[4][4];
    #pragma unroll
    for (int i = 0; i < 4; i++)
        #pragma unroll
        for (int j = 0; j < 4; j++) acc[i][j] = 0.f;

    for (int k0 = 0; k0 < K; k0 += 16) {
        #pragma unroll
        for (int i = 0; i < 4; i++) {
            int idx = tid + i * 256;
            int mr = idx >> 4, kk = idx & 15;
            int mg = m0 + mr, kg = k0 + kk;
            float av = 0.f;
            if (mg < M && kg < K) {
                if (aT)       av = A[(size_t)kg * M + mg];
                else if (A2)  av = (kg < MDIM) ? A[(size_t)mg * MDIM + kg]
                                               : A2[(size_t)mg * MDIM + (kg - MDIM)];
                else          av = A[(size_t)mg * K + kg];
            }
            As[kk][mr] = av;
        }
        #pragma unroll
        for (int i = 0; i < 4; i++) {
            int idx = tid + i * 256;
            if (!bT) {
                int kk = idx >> 6, cg = idx & 63;
                int kgl = k0 + kk, cgl = n0 + cg;
                Bs[kk][cg] = (kgl < K && cgl < N) ? B[(size_t)kgl * N + cgl] : 0.f;
            } else {
                int cg = idx >> 4, kk = idx & 15;
                int kgl = k0 + kk, cgl = n0 + cg;
                Bs[kk][cg] = (kgl < K && cgl < N) ? B[(size_t)cgl * K + kgl] : 0.f;
            }
        }
        __syncthreads();
        #pragma unroll
        for (int kk = 0; kk < 16; kk++) {
            float a[4], bb[4];
            #pragma unroll
            for (int i = 0; i < 4; i++) a[i] = As[kk][ty * 4 + i];
            #pragma unroll
            for (int j = 0; j < 4; j++) bb[j] = Bs[kk][tx * 4 + j];
            #pragma unroll
            for (int i = 0; i < 4; i++)
                #pragma unroll
                for (int j = 0; j < 4; j++) acc[i][j] += a[i] * bb[j];
        }
        __syncthreads();
    }

    #pragma unroll
    for (int i = 0; i < 4; i++) {
        int mg = m0 + ty * 4 + i;
        if (mg >= M) continue;
        #pragma unroll
        for (int j = 0; j < 4; j++) {
            int ng = n0 + tx * 4 + j;
            if (ng >= N) continue;
            float v = acc[i][j];
            if (bias) v += bias[ng];
            if (mode == 1)      v = fmaxf(v, 0.f);
            else if (mode == 2) v *= (1.0f / 6.0f);
            if (mode == 4) {
                v = ((mg == ng) ? 1.f : 0.f) - v;
                E[(size_t)mg * DTOT + ng] = v;
                if (mg >= MDIM)
                    C[(size_t)((mg - MDIM) >> 1) * 1024 + ng * 2 + ((mg - MDIM) & 1)] = v;
            } else if (mode == 6) {
                C[(size_t)mg * N + ng] = 0.3f * E[(size_t)mg * N + ng] - 1.8f * v;
            } else {
                C[(size_t)mg * N + ng] = v;
            }
        }
    }
}

// L1: X1 | Q | P (dual store)
__global__ void precompute1(const float* b, const float* cin,
                            const float* W1, const float* b1,
                            const float* Aaug, const float* Ainv,
                            float* X1, float* Q, float* P2, float* Pn)
{
    int z = blockIdx.z;
    if (z == 0) {
        gemm_dev(b, cin, W1, b1, X1, nullptr, BATCH, HDIM, DTOT, 1, 0, 0);
    } else if (z == 1) {
        gemm_dev(b, nullptr, Ainv, nullptr, Q, nullptr, BATCH, DTOT, MDIM, 0, 1, 0);
    } else {
        if (blockIdx.y >= 8) return;
        gemm_dev(Aaug, nullptr, Ainv, nullptr, P2, Pn, DTOT, DTOT, MDIM, 4, 1, 1);
    }
}

// L2: X2 | W3P' = (W3@P)/6 | b3P' = (b3@P)/6
__global__ void precompute2(const float* X1, const float* W2, const float* b2,
                            const float* W3, const float* b3, const float* Pn,
                            float* X2, float* W3P, float* b3P)
{
    int z = blockIdx.z;
    if (z == 0) {
        gemm_dev(X1, nullptr, W2, b2, X2, nullptr, BATCH, HDIM, HDIM, 1, 0, 0);
    } else if (z == 1) {
        if (blockIdx.y >= 8) return;
        gemm_dev(W3, nullptr, Pn, nullptr, W3P, nullptr, HDIM, DTOT, DTOT, 2, 0, 0);
    } else {
        if (blockIdx.y >= 1) return;
        gemm_dev(b3, nullptr, Pn, nullptr, b3P, nullptr, 1, DTOT, DTOT, 2, 0, 0);
    }
}

// L3: Ys | C0 = 0.3 Q - 1.8 (X2 @ W3P' + b3P')
__global__ void precompute3(const float* X2, const float* W3, const float* b3,
                            const float* W3P, const float* b3P, const float* Q,
                            float* Ys, float* C0)
{
    int z = blockIdx.z;
    if (z == 0) {
        gemm_dev(X2, nullptr, W3, b3, Ys, nullptr, BATCH, DTOT, HDIM, 2, 0, 0);
    } else {
        gemm_dev(X2, nullptr, W3P, b3P, C0, const_cast<float*>(Q),
                 BATCH, DTOT, HDIM, 6, 0, 0);
    }
}

// ---------------------------------------------------------------------------
// Solver smem (floats):
//  Dsm[2048] | Pz[8192] | red[128] nrm[8] tls[8] pad->10496 |
//  Pcs[40*1024=40960]        total 51456 f = 205,824 B
// ---------------------------------------------------------------------------
#define SMEM_FLOATS (10496 + 40 * 1024)
#define SMEM_BYTES  (SMEM_FLOATS * 4)

__device__ __forceinline__ float soc_elem(float tp, int c, float nu, float tt)
{
    if (c < MDIM) return tp;
    if (nu <= tt) return tp;
    if (nu <= -tt) return 0.f;
    float h = 0.5f * (tt + nu);
    return (c == DTOT - 1) ? h : h * tp / (nu + 1e-12f);
}

// Register buffer: one streamed step = 2 k-pairs x this warp's 64-col slice.
struct PB { ulonglong2 p0, p1; };

__device__ __forceinline__ PB ldg_step(int st, int g, int cg, int lane)
{
    const float* src = g_P2 + (g * 64 + 2 * st) * 1024 + cg * 128 + lane * 4;
    PB b;
    b.p0 = *reinterpret_cast<const ulonglong2*>(src);          // kp even
    b.p1 = *reinterpret_cast<const ulonglong2*>(src + 1024);   // kp odd
    return b;
}

// Partial w = delta @ P2 over kgroup g for 2 cols x 8 rows -> Pz.
// pb[0..1] hold steps 0,1 on entry; on exit they hold steps 0,1 for the NEXT
// iteration (prefetch wraps: P2 addresses are iteration-invariant).
__device__ __forceinline__ void gemm_partial(const float* __restrict__ Dsm,
                                             const float* __restrict__ Pcs,
                                             float* __restrict__ Pz,
                                             PB* pb, int g, int cg, int lane)
{
    ull acc[8][2];
    #pragma unroll
    for (int r = 0; r < 8; r++) { acc[r][0] = 0ull; acc[r][1] = 0ull; }

    // ---- streamed phase: 22 steps x 2 kp (kp 0..43 of group) ----
    #pragma unroll 2
    for (int st = 0; st < NSTR; st++) {
        const int sl = st & 1;                 // static after unroll 2
        ulonglong2 p0 = pb[sl].p0;
        ulonglong2 p1 = pb[sl].p1;
        int pf = st + 2; if (pf >= NSTR) pf -= NSTR;   // wraps to next iter
        pb[sl] = ldg_step(pf, g, cg, lane);

        const int kf = g * 128 + 4 * st;
        #pragma unroll
        for (int r = 0; r < 8; r++) {
            ulonglong2 sv = *reinterpret_cast<const ulonglong2*>(&Dsm[r * 256 + kf]);
            FFMA2(acc[r][0], sv.x, p0.x);  FFMA2(acc[r][1], sv.x, p0.y);
            FFMA2(acc[r][0], sv.y, p1.x);  FFMA2(acc[r][1], sv.y, p1.y);
        }
    }

    // ---- cached phase: 10 steps x 2 kp (kp 44..63 of group, smem) ----
    #pragma unroll
    for (int j = 0; j < NCACHE; j++) {
        const float* cp0 = &Pcs[(g * 20 + 2 * j) * 1024 + cg * 128 + lane * 4];
        ulonglong2 p0 = *reinterpret_cast<const ulonglong2*>(cp0);
        ulonglong2 p1 = *reinterpret_cast<const ulonglong2*>(cp0 + 1024);
        const int kf = g * 128 + 88 + 4 * j;
        #pragma unroll
        for (int r = 0; r < 8; r++) {
            ulonglong2 sv = *reinterpret_cast<const ulonglong2*>(&Dsm[r * 256 + kf]);
            FFMA2(acc[r][0], sv.x, p0.x);  FFMA2(acc[r][1], sv.x, p0.y);
            FFMA2(acc[r][0], sv.y, p1.x);  FFMA2(acc[r][1], sv.y, p1.y);
        }
    }

    float* dst = &Pz[g * 4096 + cg * 64 + 2 * lane];
    #pragma unroll
    for (int r = 0; r < 8; r++) {
        float2 u0 = f32x2_unpack(acc[r][0]);
        float2 u1 = f32x2_unpack(acc[r][1]);
        float2 v; v.x = u0.x + u0.y; v.y = u1.x + u1.y;
        *reinterpret_cast<float2*>(&dst[r * 512]) = v;
    }
}

__global__ void __launch_bounds__(NTHR, 1) solver_kernel(float* __restrict__ out,
                                                         int start_it, int end_it)
{
    extern __shared__ float sm[];
    float* Dsm  = sm;              // 2048 (8 rows x 256 local-k, zero-padded)
    float* Pz   = sm + 2048;       // 8192
    float* red  = sm + 10240;      // 128
    float* nrm  = sm + 10368;      // 8
    float* tls  = sm + 10376;      // 8
    float* Pcs  = sm + 10496;      // 40*1024

    const int t = threadIdx.x;
    const int w = t >> 5, lane = t & 31;
    const int g = w & 1, cg = w >> 1;
    const int row0 = blockIdx.x * ROWS_PER_CTA;
    const int c = t;
    const bool act = (c < DTOT);

    // persistent per-thread state
    float s[8], z[8], ys[8], c0[8];
    #pragma unroll
    for (int r = 0; r < 8; r++) {
        if (act) {
            int idx = (row0 + r) * DTOT + c;
            ys[r] = g_Ys[idx];
            c0[r] = g_C0[idx];
            if (start_it == 0) { s[r] = 0.f; z[r] = g_Q[idx]; }
            else               { s[r] = g_S[idx]; z[r] = g_Z[idx]; }
        } else { s[r] = 0.f; z[r] = 0.f; ys[r] = 0.f; c0[r] = 0.f; }
    }

    // Dsm zero; P cache fill (kp = group*64 + 44 + j, j<20)
    for (int i = t; i < ROWS_PER_CTA * 256; i += NTHR) Dsm[i] = 0.f;
    {
        float4* dstv = reinterpret_cast<float4*>(Pcs);
        #pragma unroll 1
        for (int i4 = t; i4 < 40 * 256; i4 += NTHR) {
            int sidx = i4 >> 8, within = i4 & 255;
            int kp = (sidx / 20) * 64 + 44 + (sidx % 20);
            dstv[i4] = *reinterpret_cast<const float4*>(&g_P2[kp * 1024 + within * 4]);
        }
    }
    __syncthreads();

    // prologue: steps 0,1 in registers (stays primed across iterations)
    PB pb[2];
    pb[0] = ldg_step(0, g, cg, lane);
    pb[1] = ldg_step(1, g, cg, lane);

    const bool in_u = act && (c >= MDIM) && (c != DTOT - 1);

    for (int it = start_it; it < end_it; ++it) {
        // ---- elementwise: toproj + ssq partials ----
        float tp[8], val[8];
        #pragma unroll
        for (int r = 0; r < 8; r++) {
            tp[r]  = act ? (ALPHA_F * (2.f * z[r] - s[r]) - ys[r]) : 0.f;
            val[r] = in_u ? tp[r] * tp[r] : 0.f;
        }
        #pragma unroll
        for (int off = 16; off; off >>= 1)
            #pragma unroll
            for (int r = 0; r < 8; r++)
                val[r] += __shfl_down_sync(0xffffffffu, val[r], off);
        if (lane == 0) {
            #pragma unroll
            for (int r = 0; r < 8; r++) red[w * 8 + r] = val[r];
        }
        if (t == DTOT - 1) {
            #pragma unroll
            for (int r = 0; r < 8; r++) tls[r] = tp[r];
        }
        __syncthreads();                               // B1
        if (w < 8 && lane < 16) {                      // warp w reduces row w
            float sv = red[lane * 8 + w];
            #pragma unroll
            for (int off = 8; off; off >>= 1)
                sv += __shfl_down_sync(0x0000ffffu, sv, off);
            if (lane == 0) nrm[w] = sqrtf(sv);
        }
        __syncthreads();                               // B2
        // ---- tk, delta, s-update ----
        if (act) {
            #pragma unroll
            for (int r = 0; r < 8; r++) {
                float tk = soc_elem(tp[r], c, nrm[r], tls[r]);
                s[r] += OMEGA_F * (tk - z[r]);
                if (c >= MDIM) Dsm[r * 256 + (c - MDIM)] = tk - tp[r];
            }
        }
        __syncthreads();                               // B3: delta visible
        gemm_partial(Dsm, Pcs, Pz, pb, g, cg, lane);
        __syncthreads();                               // B4: partials ready
        // ---- z-recursion ----
        if (act) {
            #pragma unroll
            for (int r = 0; r < 8; r++) {
                float wv = Pz[r * 512 + c] + Pz[4096 + r * 512 + c];
                z[r] = 0.7f * z[r] + c0[r] + 1.8f * wv;
            }
        }
    }

    if (end_it == NITER) {
        if (act) {
            #pragma unroll
            for (int r = 0; r < 8; r++)
                out[(row0 + r) * DTOT + c] = z[r];
        }
    } else if (act) {
        #pragma unroll
        for (int r = 0; r < 8; r++) {
            int idx = (row0 + r) * DTOT + c;
            g_S[idx] = s[r];
            g_Z[idx] = z[r];
        }
    }
}

// ---------------------------------------------------------------------------
extern "C" void kernel_launch(void* const* d_in, const int* in_sizes, int n_in,
                              void* d_out, int out_size)
{
    const float* b    = (const float*)d_in[0];
    const float* cin  = (const float*)d_in[1];
    const float* W1   = (const float*)d_in[2];
    const float* b1   = (const float*)d_in[3];
    const float* W2   = (const float*)d_in[4];
    const float* b2   = (const float*)d_in[5];
    const float* W3   = (const float*)d_in[6];
    const float* b3   = (const float*)d_in[7];
    const float* Aaug = (const float*)d_in[8];
    const float* Ainv = (const float*)d_in[9];
    float* out = (float*)d_out;

    float *X1, *X2, *Ys, *Q, *C0, *Pn, *P2, *W3P, *b3P;
    cudaGetSymbolAddress((void**)&X1,  g_X1);
    cudaGetSymbolAddress((void**)&X2,  g_X2);
    cudaGetSymbolAddress((void**)&Ys,  g_Ys);
    cudaGetSymbolAddress((void**)&Q,   g_Q);
    cudaGetSymbolAddress((void**)&C0,  g_C0);
    cudaGetSymbolAddress((void**)&Pn,  g_Pn);
    cudaGetSymbolAddress((void**)&P2,  g_P2);
    cudaGetSymbolAddress((void**)&W3P, g_W3P);
    cudaGetSymbolAddress((void**)&b3P, g_b3P);

    cudaFuncSetAttribute(solver_kernel,
                         cudaFuncAttributeMaxDynamicSharedMemorySize, SMEM_BYTES);

    // L1..L3: precompute (solver = global launch #6 under ncu -s 5 -c 1)
    precompute1<<<dim3(8, 16, 3), 256>>>(b, cin, W1, b1, Aaug, Ainv, X1, Q, P2, Pn);
    precompute2<<<dim3(8, 16, 3), 256>>>(X1, W2, b2, W3, b3, Pn, X2, W3P, b3P);
    precompute3<<<dim3(8, 16, 2), 256>>>(X2, W3, b3, W3P, b3P, Q, Ys, C0);
    // L4..L7: solver chunks
    for (int ch = 0; ch < NCHUNK; ch++)
        solver_kernel<<<SOLVER_CTAS, NTHR, SMEM_BYTES>>>(out, ch * CHUNK, (ch + 1) * CHUNK);
}